// round 2
// baseline (speedup 1.0000x reference)
#include <cuda_runtime.h>

// out[b,h,w] = sum_c x[b,h,w,c] * sigmoid(12*(sigmoid(5*w[h%8,w%8,c]) - thresh[h%8,w%8,c]))
// x: (32,512,512,4) fp32 NHWC, w/thresh: (1,8,8,4) fp32, out: (32,512,512,1) fp32.
//
// R1 insight: L1 pipe was the limiter (80%) due to shared-memory mask loads.
// Fix: stride each thread by 1024 quads (= 4096 pixels = 8 rows), which keeps
// (h%8, w%8) invariant per thread -> mask lives in 16 registers, zero LDS in
// the hot loop. Hot loop per iter: 4x LDG.128 + 1x STG.128 + 16 FMA only.

#define PMASK_SLOPE 5.0f
#define SAMPLE_SLOPE 12.0f

#define NQUADS   (32 * 512 * 512 / 4)   // 2,097,152
#define NTHREADS 131072                 // 512 blocks x 256; multiple of 1024
#define NITERS   (NQUADS / NTHREADS)    // 16

__device__ __forceinline__ float sigmoidf(float z) {
    return 1.0f / (1.0f + __expf(-z));
}

__device__ __forceinline__ float4 mask4(float4 w4, float4 t4) {
    float4 m;
    m.x = sigmoidf(SAMPLE_SLOPE * (sigmoidf(PMASK_SLOPE * w4.x) - t4.x));
    m.y = sigmoidf(SAMPLE_SLOPE * (sigmoidf(PMASK_SLOPE * w4.y) - t4.y));
    m.z = sigmoidf(SAMPLE_SLOPE * (sigmoidf(PMASK_SLOPE * w4.z) - t4.z));
    m.w = sigmoidf(SAMPLE_SLOPE * (sigmoidf(PMASK_SLOPE * w4.w) - t4.w));
    return m;
}

__global__ void __launch_bounds__(256, 4)
probmask_kernel(const float4* __restrict__ x,
                const float4* __restrict__ wv,
                const float4* __restrict__ tv,
                float4* __restrict__ out)
{
    int t = blockIdx.x * blockDim.x + threadIdx.x;   // 0..131071

    // First quad for this thread; stride of NTHREADS quads = 4*NTHREADS pixels,
    // which is a multiple of 4096 -> (h%8, w%8) invariant across iterations.
    int i0 = t << 2;                   // flat pixel index of first quad
    int h8 = (i0 >> 9) & 7;
    int wb = i0 & 7;                   // 0 or 4
    int mbase = (h8 << 3) + wb;

    // Compute the 4 per-pixel channel masks once, into registers.
    float4 m0 = mask4(wv[mbase + 0], tv[mbase + 0]);
    float4 m1 = mask4(wv[mbase + 1], tv[mbase + 1]);
    float4 m2 = mask4(wv[mbase + 2], tv[mbase + 2]);
    float4 m3 = mask4(wv[mbase + 3], tv[mbase + 3]);

    #pragma unroll
    for (int it = 0; it < NITERS; it++) {
        int q = t + it * NTHREADS;     // quad index
        int p = q << 2;                // pixel index

        float4 p0 = x[p + 0];
        float4 p1 = x[p + 1];
        float4 p2 = x[p + 2];
        float4 p3 = x[p + 3];

        float4 r;
        r.x = p0.x * m0.x + p0.y * m0.y + p0.z * m0.z + p0.w * m0.w;
        r.y = p1.x * m1.x + p1.y * m1.y + p1.z * m1.z + p1.w * m1.w;
        r.z = p2.x * m2.x + p2.y * m2.y + p2.z * m2.z + p2.w * m2.w;
        r.w = p3.x * m3.x + p3.y * m3.y + p3.z * m3.z + p3.w * m3.w;

        out[q] = r;
    }
}

extern "C" void kernel_launch(void* const* d_in, const int* in_sizes, int n_in,
                              void* d_out, int out_size)
{
    const float4* x  = (const float4*)d_in[0];
    const float4* wv = (const float4*)d_in[1];
    const float4* tv = (const float4*)d_in[2];
    float4* out = (float4*)d_out;

    probmask_kernel<<<NTHREADS / 256, 256>>>(x, wv, tv, out);
}

// round 3
// speedup vs baseline: 1.1887x; 1.1887x over previous
#include <cuda_runtime.h>

// out[b,h,w] = sum_c x[b,h,w,c] * mask[h%8,w%8,c],
// mask = sigmoid(12*(sigmoid(5*w) - thresh)), x: (32,512,512,4) fp32 NHWC.
//
// R1: LDS-in-loop bound L1 at 80% -> DRAM 65.5%, 28.6us.
// R2: register masks but grid=512/regs=64 -> occ 41%, DRAM 57.8%, 32.7us.
// R3: both fixes: big grid (2048 blocks) + smem-built mask table pulled into
//     registers once per thread (stride multiple of 8 rows keeps (h%8,w%8)
//     invariant). Hot loop: 4x LDG.128 + 16 FFMA + 1x STG.128 only.

#define PMASK_SLOPE 5.0f
#define SAMPLE_SLOPE 12.0f

#define NQUADS   (32 * 512 * 512 / 4)   // 2,097,152
#define NTHREADS (2048 * 256)           // 524,288; stride mult. of 1024 quads
#define NITERS   (NQUADS / NTHREADS)    // 4

__device__ __forceinline__ float sigmoidf(float z) {
    return 1.0f / (1.0f + __expf(-z));
}

__global__ void __launch_bounds__(256)
probmask_kernel(const float4* __restrict__ x,
                const float4* __restrict__ wv,
                const float4* __restrict__ tv,
                float4* __restrict__ out)
{
    __shared__ float4 smask[64];   // [h8*8 + w8] -> per-channel mask

    int tid = threadIdx.x;
    if (tid < 64) {
        float4 w4 = wv[tid];
        float4 t4 = tv[tid];
        float4 m;
        m.x = sigmoidf(SAMPLE_SLOPE * (sigmoidf(PMASK_SLOPE * w4.x) - t4.x));
        m.y = sigmoidf(SAMPLE_SLOPE * (sigmoidf(PMASK_SLOPE * w4.y) - t4.y));
        m.z = sigmoidf(SAMPLE_SLOPE * (sigmoidf(PMASK_SLOPE * w4.z) - t4.z));
        m.w = sigmoidf(SAMPLE_SLOPE * (sigmoidf(PMASK_SLOPE * w4.w) - t4.w));
        smask[tid] = m;
    }
    __syncthreads();

    int t = blockIdx.x * blockDim.x + tid;   // 0..524287

    // (h%8, w%8) of this thread's quads is invariant across iterations:
    // stride = NTHREADS quads = 4*NTHREADS pixels, a multiple of 4096 (8 rows).
    int i0 = t << 2;
    int mbase = (((i0 >> 9) & 7) << 3) + (i0 & 7);

    float4 m0 = smask[mbase + 0];
    float4 m1 = smask[mbase + 1];
    float4 m2 = smask[mbase + 2];
    float4 m3 = smask[mbase + 3];

    #pragma unroll 2
    for (int it = 0; it < NITERS; it++) {
        int q = t + it * NTHREADS;   // quad index
        int p = q << 2;              // pixel index

        float4 p0 = x[p + 0];
        float4 p1 = x[p + 1];
        float4 p2 = x[p + 2];
        float4 p3 = x[p + 3];

        float4 r;
        r.x = p0.x * m0.x + p0.y * m0.y + p0.z * m0.z + p0.w * m0.w;
        r.y = p1.x * m1.x + p1.y * m1.y + p1.z * m1.z + p1.w * m1.w;
        r.z = p2.x * m2.x + p2.y * m2.y + p2.z * m2.z + p2.w * m2.w;
        r.w = p3.x * m3.x + p3.y * m3.y + p3.z * m3.z + p3.w * m3.w;

        out[q] = r;
    }
}

extern "C" void kernel_launch(void* const* d_in, const int* in_sizes, int n_in,
                              void* d_out, int out_size)
{
    const float4* x  = (const float4*)d_in[0];
    const float4* wv = (const float4*)d_in[1];
    const float4* tv = (const float4*)d_in[2];
    float4* out = (float4*)d_out;

    probmask_kernel<<<NTHREADS / 256, 256>>>(x, wv, tv, out);
}

// round 4
// speedup vs baseline: 1.1911x; 1.0021x over previous
#include <cuda_runtime.h>

// out[b,h,w] = sum_c x[b,h,w,c] * mask[h%8,w%8,c],
// mask = sigmoid(12*(sigmoid(5*w) - thresh)), x: (32,512,512,4) fp32 NHWC.
//
// R1-R3 all plateaued at ~66% DRAM: thread-contiguous float4 quads give LDG.128
// a 64B lane stride -> 16 cache lines per wavefront (4x the dense cost), capping
// effective L1tex bandwidth below HBM. R4: warp owns 128 consecutive pixels,
// lane l handles pixels {l, l+32, l+64, l+96} -> every LDG.128 is 512B dense
// (4 lines). w%8 = lane&7, h%8 is warp-uniform -> ONE mask float4 per thread.

#define PMASK_SLOPE 5.0f
#define SAMPLE_SLOPE 12.0f

#define NPIX        (32 * 512 * 512)      // 8,388,608 pixels
#define NTHREADS    (2048 * 256)          // 524,288
#define PIX_PER_IT  (NTHREADS * 4)        // 2,097,152 (multiple of 4096: h%8 invariant)
#define NITERS      (NPIX / PIX_PER_IT)   // 4

__device__ __forceinline__ float sigmoidf(float z) {
    return 1.0f / (1.0f + __expf(-z));
}

__global__ void __launch_bounds__(256)
probmask_kernel(const float4* __restrict__ x,
                const float4* __restrict__ wv,
                const float4* __restrict__ tv,
                float* __restrict__ out)
{
    __shared__ float4 smask[64];   // [h8*8 + w8] -> per-channel mask

    int tid = threadIdx.x;
    if (tid < 64) {
        float4 w4 = wv[tid];
        float4 t4 = tv[tid];
        float4 m;
        m.x = sigmoidf(SAMPLE_SLOPE * (sigmoidf(PMASK_SLOPE * w4.x) - t4.x));
        m.y = sigmoidf(SAMPLE_SLOPE * (sigmoidf(PMASK_SLOPE * w4.y) - t4.y));
        m.z = sigmoidf(SAMPLE_SLOPE * (sigmoidf(PMASK_SLOPE * w4.z) - t4.z));
        m.w = sigmoidf(SAMPLE_SLOPE * (sigmoidf(PMASK_SLOPE * w4.w) - t4.w));
        smask[tid] = m;
    }
    __syncthreads();

    int lane  = tid & 31;
    int gwarp = (blockIdx.x * blockDim.x + tid) >> 5;   // 0..16383
    int base0 = gwarp << 7;                             // warp's first pixel (mult of 128)

    // h%8 is identical for all 128 pixels of the warp tile (row = 512 px),
    // and invariant across iterations (stride PIX_PER_IT % 4096 == 0).
    // w%8 of lane's pixels = lane & 7 (stride 32 within the tile).
    int h8 = (base0 >> 9) & 7;
    float4 m = smask[(h8 << 3) + (lane & 7)];

    #pragma unroll 2
    for (int it = 0; it < NITERS; it++) {
        int p = base0 + it * PIX_PER_IT + lane;

        float4 v0 = x[p +  0];
        float4 v1 = x[p + 32];
        float4 v2 = x[p + 64];
        float4 v3 = x[p + 96];

        out[p +  0] = v0.x * m.x + v0.y * m.y + v0.z * m.z + v0.w * m.w;
        out[p + 32] = v1.x * m.x + v1.y * m.y + v1.z * m.z + v1.w * m.w;
        out[p + 64] = v2.x * m.x + v2.y * m.y + v2.z * m.z + v2.w * m.w;
        out[p + 96] = v3.x * m.x + v3.y * m.y + v3.z * m.z + v3.w * m.w;
    }
}

extern "C" void kernel_launch(void* const* d_in, const int* in_sizes, int n_in,
                              void* d_out, int out_size)
{
    const float4* x  = (const float4*)d_in[0];
    const float4* wv = (const float4*)d_in[1];
    const float4* tv = (const float4*)d_in[2];
    float* out = (float*)d_out;

    probmask_kernel<<<NTHREADS / 256, 256>>>(x, wv, tv, out);
}

// round 7
// speedup vs baseline: 1.2010x; 1.0083x over previous
#include <cuda_runtime.h>

// out[b,h,w] = sum_c x[b,h,w,c] * mask[h%8,w%8,c],
// mask = sigmoid(12*(sigmoid(5*w) - thresh)), x: (32,512,512,4) fp32 NHWC.
//
// R4 structure (dense 512B warp loads, one mask float4/thread, 2048x256 grid).
// R6 = R5 theory via inline PTX instead of __ldcs/__stcs intrinsics:
//   ld.global.cs / st.global.cs (evict-first streaming: x and out are
//   single-touch, x > L2) + front-batched 8 loads per thread (MLP=8).

#define PMASK_SLOPE 5.0f
#define SAMPLE_SLOPE 12.0f

#define NPIX        (32 * 512 * 512)      // 8,388,608 pixels
#define NTHREADS    (2048 * 256)          // 524,288
#define PIX_PER_IT  (NTHREADS * 4)        // 2,097,152 (mult of 4096: h%8 invariant)
#define NITERS      (NPIX / PIX_PER_IT)   // 4

__device__ __forceinline__ float sigmoidf(float z) {
    return 1.0f / (1.0f + __expf(-z));
}

__device__ __forceinline__ float4 ldcs4(const float4* p) {
    float4 v;
    asm volatile("ld.global.cs.v4.f32 {%0,%1,%2,%3}, [%4];"
                 : "=f"(v.x), "=f"(v.y), "=f"(v.z), "=f"(v.w)
                 : "l"(p));
    return v;
}

__device__ __forceinline__ void stcs1(float* p, float v) {
    asm volatile("st.global.cs.f32 [%0], %1;" :: "l"(p), "f"(v) : "memory");
}

__device__ __forceinline__ float dot4(float4 v, float4 m) {
    return v.x * m.x + v.y * m.y + v.z * m.z + v.w * m.w;
}

__global__ void __launch_bounds__(256)
probmask_kernel(const float4* __restrict__ x,
                const float4* __restrict__ wv,
                const float4* __restrict__ tv,
                float* __restrict__ out)
{
    __shared__ float4 smask[64];   // [h8*8 + w8] -> per-channel mask

    int tid = threadIdx.x;
    if (tid < 64) {
        float4 w4 = wv[tid];
        float4 t4 = tv[tid];
        float4 m;
        m.x = sigmoidf(SAMPLE_SLOPE * (sigmoidf(PMASK_SLOPE * w4.x) - t4.x));
        m.y = sigmoidf(SAMPLE_SLOPE * (sigmoidf(PMASK_SLOPE * w4.y) - t4.y));
        m.z = sigmoidf(SAMPLE_SLOPE * (sigmoidf(PMASK_SLOPE * w4.z) - t4.z));
        m.w = sigmoidf(SAMPLE_SLOPE * (sigmoidf(PMASK_SLOPE * w4.w) - t4.w));
        smask[tid] = m;
    }
    __syncthreads();

    int lane  = tid & 31;
    int gwarp = (blockIdx.x * blockDim.x + tid) >> 5;   // 0..16383
    int base0 = gwarp << 7;                             // warp's first pixel (mult of 128)

    // h%8 warp-uniform and iteration-invariant; w%8 = lane&7.
    int h8 = (base0 >> 9) & 7;
    float4 m = smask[(h8 << 3) + (lane & 7)];

    #pragma unroll
    for (int it = 0; it < NITERS; it += 2) {
        int pa = base0 + it * PIX_PER_IT + lane;
        int pb = pa + PIX_PER_IT;

        // Front-batch 8 streaming loads (8 x 512B dense per warp).
        float4 a0 = ldcs4(&x[pa +  0]);
        float4 a1 = ldcs4(&x[pa + 32]);
        float4 a2 = ldcs4(&x[pa + 64]);
        float4 a3 = ldcs4(&x[pa + 96]);
        float4 b0 = ldcs4(&x[pb +  0]);
        float4 b1 = ldcs4(&x[pb + 32]);
        float4 b2 = ldcs4(&x[pb + 64]);
        float4 b3 = ldcs4(&x[pb + 96]);

        stcs1(&out[pa +  0], dot4(a0, m));
        stcs1(&out[pa + 32], dot4(a1, m));
        stcs1(&out[pa + 64], dot4(a2, m));
        stcs1(&out[pa + 96], dot4(a3, m));
        stcs1(&out[pb +  0], dot4(b0, m));
        stcs1(&out[pb + 32], dot4(b1, m));
        stcs1(&out[pb + 64], dot4(b2, m));
        stcs1(&out[pb + 96], dot4(b3, m));
    }
}

extern "C" void kernel_launch(void* const* d_in, const int* in_sizes, int n_in,
                              void* d_out, int out_size)
{
    const float4* x  = (const float4*)d_in[0];
    const float4* wv = (const float4*)d_in[1];
    const float4* tv = (const float4*)d_in[2];
    float* out = (float*)d_out;

    probmask_kernel<<<NTHREADS / 256, 256>>>(x, wv, tv, out);
}